// round 9
// baseline (speedup 1.0000x reference)
#include <cuda_runtime.h>
#include <stdint.h>

#define HH 721
#define WW 1440
#define NPTS (HH*WW)
#define NQ4  (NPTS/4)
#define BB 16
#define CC 4
#define DD 256
#define NV 12
#define PI_D 3.141592653589793
#define TWOPI_D (2.0*PI_D)

static __device__ double        g_dla2d[NV][HH];
static __device__ double        g_dlo2d[NV][WW];
static __device__ float         g_dla2f[NV][HH];
static __device__ float         g_dlo2f[NV][WW];
static __device__ unsigned int  g_v2gi[NV];
static __device__ unsigned char g_vmap[NPTS];
static __device__ float         g_nodes[BB*NV*CC];
static __device__ float         g_WT[4*DD*DD];      // W_layers transposed: WT[l][d][k]

__constant__ signed char c_vcode[NV][3] = {
    {-1,2,0},{1,2,0},{-1,-2,0},{1,-2,0},{0,-1,2},{0,1,2},
    {0,-1,-2},{0,1,-2},{2,0,-1},{2,0,1},{-2,0,-1},{-2,0,1}};
__constant__ int c_nbr[NV][5] = {
    {11,5,1,7,10},{0,5,7,9,8},{11,10,3,4,6},{9,4,2,6,8},
    {5,11,3,9,2},{0,11,1,9,4},{10,7,3,2,8},{0,1,10,6,8},
    {7,1,3,6,9},{1,5,3,4,8},{0,7,11,2,6},{0,5,10,2,4}};

// ---- K0: fused prep. Blocks 0..255: transpose W_layers. Blocks 256..267: f64 tables + v2g. ----
__global__ void __launch_bounds__(256) k_prep(const float* __restrict__ W) {
    int bid = blockIdx.x;
    int t = threadIdx.x;

    if (bid < 256) {                       // ---- W transpose path ----
        __shared__ float tile[32][33];
        int l = bid >> 6;
        int t6 = bid & 63;
        int k0 = (t6 & 7) * 32, d0 = (t6 >> 3) * 32;
        int tx = t & 31, ty = t >> 5;
        const float* src = W + l * DD * DD;
        float* dst = g_WT + l * DD * DD;
#pragma unroll
        for (int r = ty; r < 32; r += 8)
            tile[r][tx] = src[(k0 + r) * DD + d0 + tx];
        __syncthreads();
#pragma unroll
        for (int r = ty; r < 32; r += 8)
            dst[(d0 + r) * DD + k0 + tx] = tile[tx][r];
        return;
    }

    // ---- per-vertex table + separable argmin path ----
    int v = bid - 256;
    __shared__ double svlat, svlon;
    __shared__ double rv[8];
    __shared__ int    ri[8];
    __shared__ int    sbest[2];

    if (t == 0) {
        float phi = (float)((1.0 + sqrt(5.0)) * 0.5);
        float c[3];
#pragma unroll
        for (int k = 0; k < 3; k++) {
            int cd = c_vcode[v][k];
            float m = (cd == 2 || cd == -2) ? phi : 1.0f;
            c[k] = (cd == 0) ? 0.0f : (cd < 0 ? -m : m);
        }
        float n2 = __fadd_rn(__fadd_rn(__fmul_rn(c[0],c[0]), __fmul_rn(c[1],c[1])),
                             __fmul_rn(c[2],c[2]));
        float nrm = __fsqrt_rn(n2);
        float x = __fdiv_rn(c[0],nrm), y = __fdiv_rn(c[1],nrm), z = __fdiv_rn(c[2],nrm);
        float s = __fsqrt_rn(__fsub_rn(1.0f, __fmul_rn(z,z)));
        svlat = (double)__fmul_rn(2.0f, atan2f(z, __fadd_rn(1.0f, s)));   // XLA asin
        svlon = (double)atan2f(y, x);
    }
    __syncthreads();
    double vlat = svlat, vlon = svlon;

    double bla = 1.0e300, blo = 1.0e300; int bia = 0, bio = 0;
    double dla_s = __ddiv_rn(PI_D, 720.0);
    double dlo_s = __ddiv_rn(TWOPI_D, 1439.0);
    for (int li = t; li < HH; li += 256) {
        double lat = __dadd_rn(-(PI_D*0.5), __dmul_rn((double)li, dla_s));
        if (li == 360) lat = 1.0e-12;            // symmetry row pinned positive (validated)
        double dla = __dsub_rn(lat, vlat);
        double q = __dmul_rn(dla, dla);
        g_dla2d[v][li] = q;
        g_dla2f[v][li] = (float)q;
        if (q < bla) { bla = q; bia = li; }
    }
    for (int lj = t; lj < WW; lj += 256) {
        double lon = __dadd_rn(-PI_D, __dmul_rn((double)lj, dlo_s));
        double raw = __dadd_rn(__dsub_rn(lon, vlon), PI_D);
        double r = raw;
        if (raw >= TWOPI_D)   r = __dsub_rn(raw, TWOPI_D);
        else if (raw < 0.0)   r = __dadd_rn(raw, TWOPI_D);
        double dlo = __dsub_rn(r, PI_D);
        double q = __dmul_rn(dlo, dlo);
        g_dlo2d[v][lj] = q;
        g_dlo2f[v][lj] = (float)q;
        if (q < blo) { blo = q; bio = lj; }
    }
#pragma unroll
    for (int pass = 0; pass < 2; pass++) {
        double bv = pass ? blo : bla;
        int    bi = pass ? bio : bia;
#pragma unroll
        for (int off = 16; off > 0; off >>= 1) {
            double ov = __shfl_down_sync(0xFFFFFFFFu, bv, off);
            int    oi = __shfl_down_sync(0xFFFFFFFFu, bi, off);
            if (ov < bv || (ov == bv && oi < bi)) { bv = ov; bi = oi; }
        }
        if ((t & 31) == 0) { rv[t >> 5] = bv; ri[t >> 5] = bi; }
        __syncthreads();
        if (t < 8) {
            bv = rv[t]; bi = ri[t];
#pragma unroll
            for (int off = 4; off > 0; off >>= 1) {
                double ov = __shfl_down_sync(0xFFu, bv, off);
                int    oi = __shfl_down_sync(0xFFu, bi, off);
                if (ov < bv || (ov == bv && oi < bi)) { bv = ov; bi = oi; }
            }
            if (t == 0) sbest[pass] = bi;
        }
        __syncthreads();
    }
    if (t == 0) g_v2gi[v] = (unsigned)(sbest[0] * WW + sbest[1]);
}

// ---- K1: per-pixel nearest vertex; f32 fast path + exact f64 fallback near boundaries ----
__global__ void __launch_bounds__(256) k_vmap() {
    __shared__ float sa[NV];
    __shared__ float sb[NV][256];
    int t = threadIdx.x;
    int li = blockIdx.y;
    int lj0 = blockIdx.x * 256;
    if (t < NV) sa[t] = g_dla2f[t][li];
#pragma unroll
    for (int v = 0; v < NV; v++) {
        int lj = lj0 + t;
        sb[v][t] = (lj < WW) ? g_dlo2f[v][lj] : 1.0e30f;
    }
    __syncthreads();

    int lj = lj0 + t;
    if (lj >= WW) return;
    float b1 = 1.0e30f, b2 = 1.0e30f; int bv = 0;
#pragma unroll
    for (int v = 0; v < NV; v++) {
        float s = sa[v] + sb[v][t];
        if (s < b1) { b2 = b1; b1 = s; bv = v; }
        else if (s < b2) { b2 = s; }
    }
    if (b2 - b1 < 1.0e-4f) {   // ambiguous in f32 -> exact f64 reference compare
        double best = 1.0e300; bv = 0;
#pragma unroll
        for (int v = 0; v < NV; v++) {
            double s = __dadd_rn(g_dla2d[v][li], g_dlo2d[v][lj]);
            if (s < best) { best = s; bv = v; }
        }
    }
    int p = li * WW + lj;
    int j = p / HH;             // g2v = reshape(lon,lat).T scramble
    int i = p - j * HH;
    g_vmap[i * WW + j] = (unsigned char)bv;
}

// ---- K2: fused GNN — inproj + 4 layers + outproj. 16 blocks (one per batch) x 1024. ----
// Thread t handles d = t&255 for vertices {t>>8, (t>>8)+4, (t>>8)+8}: the weight row
// WT[l][d][*] is shared across its 3 dot products (12 FMA per LDG.128).
__global__ void __launch_bounds__(1024) k_gnn(const float* __restrict__ x,
                                              const float* __restrict__ Win,
                                              const float* __restrict__ bin,
                                              const float* __restrict__ bl,
                                              const float* __restrict__ Wout,
                                              const float* __restrict__ bout) {
    int b = blockIdx.x, t = threadIdx.x;
    __shared__ float h[NV * DD];
    __shared__ float agg[NV * DD];
    int d = t & 255, vg = t >> 8;      // vg in 0..3

    // inproj
#pragma unroll
    for (int r = 0; r < 3; r++) {
        int v = vg + r * 4;
        unsigned p = g_v2gi[v];
        int pi = p / WW, pj = p - pi * WW;
        const float* xb = x + ((long)(b * CC) * HH + pi) * WW + pj;
        float acc = __ldg(&bin[d]);
        acc = fmaf(__ldg(xb + 0L*HH*WW), __ldg(&Win[0*DD + d]), acc);
        acc = fmaf(__ldg(xb + 1L*HH*WW), __ldg(&Win[1*DD + d]), acc);
        acc = fmaf(__ldg(xb + 2L*HH*WW), __ldg(&Win[2*DD + d]), acc);
        acc = fmaf(__ldg(xb + 3L*HH*WW), __ldg(&Win[3*DD + d]), acc);
        h[v * DD + d] = acc;
    }
    __syncthreads();

    for (int l = 0; l < 4; l++) {
        // aggregate (elementwise in d)
#pragma unroll
        for (int r = 0; r < 3; r++) {
            int v = vg + r * 4;
            float s = h[c_nbr[v][0]*DD + d] + h[c_nbr[v][1]*DD + d]
                    + h[c_nbr[v][2]*DD + d] + h[c_nbr[v][3]*DD + d]
                    + h[c_nbr[v][4]*DD + d];
            agg[v * DD + d] = s * 0.2f;
        }
        __syncthreads();

        // matmul: 3 outputs share one weight row
        const float4* w4 = reinterpret_cast<const float4*>(g_WT + (l * DD + d) * DD);
        const float4* a0 = reinterpret_cast<const float4*>(agg + (vg    ) * DD);
        const float4* a1 = reinterpret_cast<const float4*>(agg + (vg + 4) * DD);
        const float4* a2 = reinterpret_cast<const float4*>(agg + (vg + 8) * DD);
        float4 q0 = make_float4(0,0,0,0), q1 = q0, q2 = q0;
#pragma unroll 8
        for (int k = 0; k < DD/4; k++) {
            float4 w = __ldg(&w4[k]);
            float4 f0 = a0[k], f1 = a1[k], f2 = a2[k];
            q0.x = fmaf(f0.x, w.x, q0.x); q0.y = fmaf(f0.y, w.y, q0.y);
            q0.z = fmaf(f0.z, w.z, q0.z); q0.w = fmaf(f0.w, w.w, q0.w);
            q1.x = fmaf(f1.x, w.x, q1.x); q1.y = fmaf(f1.y, w.y, q1.y);
            q1.z = fmaf(f1.z, w.z, q1.z); q1.w = fmaf(f1.w, w.w, q1.w);
            q2.x = fmaf(f2.x, w.x, q2.x); q2.y = fmaf(f2.y, w.y, q2.y);
            q2.z = fmaf(f2.z, w.z, q2.z); q2.w = fmaf(f2.w, w.w, q2.w);
        }
        float bias = __ldg(&bl[l * DD + d]);
        float r0 = ((q0.x + q0.y) + (q0.z + q0.w)) + bias;
        float r1 = ((q1.x + q1.y) + (q1.z + q1.w)) + bias;
        float r2 = ((q2.x + q2.y) + (q2.z + q2.w)) + bias;
        // each thread exclusively owns its 3 (v,d) slots
        h[(vg    ) * DD + d] += fmaxf(r0, 0.0f);
        h[(vg + 4) * DD + d] += fmaxf(r1, 0.0f);
        h[(vg + 8) * DD + d] += fmaxf(r2, 0.0f);
        __syncthreads();
    }

    // outproj: one warp per (v,c) pair, 48 pairs over 32 warps (2 rounds)
    int w = t >> 5, lane = t & 31;
    for (int pair = w; pair < NV * CC; pair += 32) {
        int v = pair >> 2, c = pair & 3;
        float s = 0.f;
#pragma unroll
        for (int k = lane; k < DD; k += 32)
            s = fmaf(h[v * DD + k], __ldg(&Wout[k * CC + c]), s);
#pragma unroll
        for (int off = 16; off > 0; off >>= 1)
            s += __shfl_down_sync(0xFFFFFFFFu, s, off);
        if (lane == 0) g_nodes[(b * NV + v) * CC + c] = s + __ldg(&bout[c]);
    }
}

// ---- K3: output scatter (write-bound) ----
__global__ void __launch_bounds__(256) k_scatter(float* __restrict__ out) {
    int b = blockIdx.z, c = blockIdx.y;
    __shared__ float sval[NV];
    if (threadIdx.x < NV) sval[threadIdx.x] = g_nodes[(b * NV + threadIdx.x) * CC + c];
    __syncthreads();
    int q = blockIdx.x * 256 + threadIdx.x;
    if (q < NQ4) {
        uchar4 vm = reinterpret_cast<const uchar4*>(g_vmap)[q];
        float4 o;
        o.x = sval[vm.x]; o.y = sval[vm.y]; o.z = sval[vm.z]; o.w = sval[vm.w];
        reinterpret_cast<float4*>(out)[(long)(b * CC + c) * NQ4 + q] = o;
    }
}

extern "C" void kernel_launch(void* const* d_in, const int* in_sizes, int n_in,
                              void* d_out, int out_size) {
    const float* x        = (const float*)d_in[0];
    const float* W_in     = (const float*)d_in[2];
    const float* b_in     = (const float*)d_in[3];
    const float* W_layers = (const float*)d_in[4];
    const float* b_layers = (const float*)d_in[5];
    const float* W_out    = (const float*)d_in[6];
    const float* b_out    = (const float*)d_in[7];
    float* out = (float*)d_out;

    k_prep<<<268, 256>>>(W_layers);
    k_vmap<<<dim3((WW + 255) / 256, HH), 256>>>();
    k_gnn<<<BB, 1024>>>(x, W_in, b_in, b_layers, W_out, b_out);
    k_scatter<<<dim3((NQ4 + 255) / 256, CC, BB), 256>>>(out);
}

// round 10
// speedup vs baseline: 1.5667x; 1.5667x over previous
#include <cuda_runtime.h>
#include <stdint.h>

#define HH 721
#define WW 1440
#define NPTS (HH*WW)
#define NQ4  (NPTS/4)
#define BB 16
#define CC 4
#define DD 256
#define NV 12
#define PI_D 3.141592653589793
#define TWOPI_D (2.0*PI_D)

static __device__ double        g_dla2d[NV][HH];
static __device__ double        g_dlo2d[NV][WW];
static __device__ float         g_dla2f[NV][HH];
static __device__ float         g_dlo2f[NV][WW];
static __device__ unsigned int  g_v2gi[NV];
static __device__ unsigned char g_vmap[NPTS];
static __device__ float         g_nodes[BB*NV*CC];
static __device__ float4        g_WT4[4*DD*DD/4];   // W transposed, float4-aligned: WT[l][d][k]

__constant__ signed char c_vcode[NV][3] = {
    {-1,2,0},{1,2,0},{-1,-2,0},{1,-2,0},{0,-1,2},{0,1,2},
    {0,-1,-2},{0,1,-2},{2,0,-1},{2,0,1},{-2,0,-1},{-2,0,1}};
__constant__ int c_nbr[NV][5] = {
    {11,5,1,7,10},{0,5,7,9,8},{11,10,3,4,6},{9,4,2,6,8},
    {5,11,3,9,2},{0,11,1,9,4},{10,7,3,2,8},{0,1,10,6,8},
    {7,1,3,6,9},{1,5,3,4,8},{0,7,11,2,6},{0,5,10,2,4}};

// ---- K0: fused prep. Blocks 0..255: transpose W. Blocks 256..267: f64 tables + v2g. ----
__global__ void __launch_bounds__(256) k_prep(const float* __restrict__ W) {
    int bid = blockIdx.x;
    int t = threadIdx.x;

    if (bid < 256) {                       // ---- W transpose ----
        __shared__ float tile[32][33];
        int l = bid >> 6;
        int t6 = bid & 63;
        int k0 = (t6 & 7) * 32, d0 = (t6 >> 3) * 32;
        int tx = t & 31, ty = t >> 5;
        const float* src = W + l * DD * DD;
        float* dst = (float*)g_WT4 + l * DD * DD;
#pragma unroll
        for (int r = ty; r < 32; r += 8)
            tile[r][tx] = src[(k0 + r) * DD + d0 + tx];
        __syncthreads();
#pragma unroll
        for (int r = ty; r < 32; r += 8)
            dst[(d0 + r) * DD + k0 + tx] = tile[tx][r];
        return;
    }

    // ---- per-vertex f64 tables + separable argmin (lex tie-break == first-index) ----
    int v = bid - 256;
    __shared__ double svlat, svlon;
    __shared__ double rv[8];
    __shared__ int    ri[8];
    __shared__ int    sbest[2];

    if (t == 0) {
        float phi = (float)((1.0 + sqrt(5.0)) * 0.5);
        float c[3];
#pragma unroll
        for (int k = 0; k < 3; k++) {
            int cd = c_vcode[v][k];
            float m = (cd == 2 || cd == -2) ? phi : 1.0f;
            c[k] = (cd == 0) ? 0.0f : (cd < 0 ? -m : m);
        }
        float n2 = __fadd_rn(__fadd_rn(__fmul_rn(c[0],c[0]), __fmul_rn(c[1],c[1])),
                             __fmul_rn(c[2],c[2]));
        float nrm = __fsqrt_rn(n2);
        float x = __fdiv_rn(c[0],nrm), y = __fdiv_rn(c[1],nrm), z = __fdiv_rn(c[2],nrm);
        float s = __fsqrt_rn(__fsub_rn(1.0f, __fmul_rn(z,z)));
        svlat = (double)__fmul_rn(2.0f, atan2f(z, __fadd_rn(1.0f, s)));   // XLA asin
        svlon = (double)atan2f(y, x);
    }
    __syncthreads();
    double vlat = svlat, vlon = svlon;

    double bla = 1.0e300, blo = 1.0e300; int bia = 0, bio = 0;
    double dla_s = __ddiv_rn(PI_D, 720.0);
    double dlo_s = __ddiv_rn(TWOPI_D, 1439.0);
    for (int li = t; li < HH; li += 256) {
        double lat = __dadd_rn(-(PI_D*0.5), __dmul_rn((double)li, dla_s));
        if (li == 360) lat = 1.0e-12;            // symmetry row pinned positive (validated)
        double dla = __dsub_rn(lat, vlat);
        double q = __dmul_rn(dla, dla);
        g_dla2d[v][li] = q;
        g_dla2f[v][li] = (float)q;
        if (q < bla) { bla = q; bia = li; }
    }
    for (int lj = t; lj < WW; lj += 256) {
        double lon = __dadd_rn(-PI_D, __dmul_rn((double)lj, dlo_s));
        double raw = __dadd_rn(__dsub_rn(lon, vlon), PI_D);
        double r = raw;
        if (raw >= TWOPI_D)   r = __dsub_rn(raw, TWOPI_D);
        else if (raw < 0.0)   r = __dadd_rn(raw, TWOPI_D);
        double dlo = __dsub_rn(r, PI_D);
        double q = __dmul_rn(dlo, dlo);
        g_dlo2d[v][lj] = q;
        g_dlo2f[v][lj] = (float)q;
        if (q < blo) { blo = q; bio = lj; }
    }
#pragma unroll
    for (int pass = 0; pass < 2; pass++) {
        double bv = pass ? blo : bla;
        int    bi = pass ? bio : bia;
#pragma unroll
        for (int off = 16; off > 0; off >>= 1) {
            double ov = __shfl_down_sync(0xFFFFFFFFu, bv, off);
            int    oi = __shfl_down_sync(0xFFFFFFFFu, bi, off);
            if (ov < bv || (ov == bv && oi < bi)) { bv = ov; bi = oi; }
        }
        if ((t & 31) == 0) { rv[t >> 5] = bv; ri[t >> 5] = bi; }
        __syncthreads();
        if (t < 8) {
            bv = rv[t]; bi = ri[t];
#pragma unroll
            for (int off = 4; off > 0; off >>= 1) {
                double ov = __shfl_down_sync(0xFFu, bv, off);
                int    oi = __shfl_down_sync(0xFFu, bi, off);
                if (ov < bv || (ov == bv && oi < bi)) { bv = ov; bi = oi; }
            }
            if (t == 0) sbest[pass] = bi;
        }
        __syncthreads();
    }
    if (t == 0) g_v2gi[v] = (unsigned)(sbest[0] * WW + sbest[1]);
}

// ---- K1: per-pixel nearest vertex; f32 fast path + exact f64 fallback near boundaries ----
__global__ void __launch_bounds__(256) k_vmap() {
    __shared__ float sa[NV];
    __shared__ float sb[NV][256];
    int t = threadIdx.x;
    int li = blockIdx.y;
    int lj0 = blockIdx.x * 256;
    if (t < NV) sa[t] = g_dla2f[t][li];
#pragma unroll
    for (int v = 0; v < NV; v++) {
        int lj = lj0 + t;
        sb[v][t] = (lj < WW) ? g_dlo2f[v][lj] : 1.0e30f;
    }
    __syncthreads();

    int lj = lj0 + t;
    if (lj >= WW) return;
    float b1 = 1.0e30f, b2 = 1.0e30f; int bv = 0;
#pragma unroll
    for (int v = 0; v < NV; v++) {
        float s = sa[v] + sb[v][t];
        if (s < b1) { b2 = b1; b1 = s; bv = v; }
        else if (s < b2) { b2 = s; }
    }
    if (b2 - b1 < 1.0e-4f) {   // ambiguous in f32 -> exact f64 reference compare
        double best = 1.0e300; bv = 0;
#pragma unroll
        for (int v = 0; v < NV; v++) {
            double s = __dadd_rn(g_dla2d[v][li], g_dlo2d[v][lj]);
            if (s < best) { best = s; bv = v; }
        }
    }
    int p = li * WW + lj;
    int j = p / HH;             // g2v = reshape(lon,lat).T scramble
    int i = p - j * HH;
    g_vmap[i * WW + j] = (unsigned char)bv;
}

// ---- K2: fused GNN with coalesced shared-staged weights. 16 blocks x 1024. ----
// Thread t: d = t&255, vertices {vg, vg+4, vg+8} (vg = t>>8). Weight row shared across
// 3 dot products. W tiles (256d x 16k) staged coalesced into smem each chunk.
__global__ void __launch_bounds__(1024) k_gnn(const float* __restrict__ x,
                                              const float* __restrict__ Win,
                                              const float* __restrict__ bin,
                                              const float* __restrict__ bl,
                                              const float* __restrict__ Wout,
                                              const float* __restrict__ bout) {
    int b = blockIdx.x, t = threadIdx.x;
    __shared__ __align__(16) float h[NV * DD];
    __shared__ __align__(16) float agg[NV * DD];
    __shared__ float4 tile4[4][DD + 4];       // [k-subchunk][d], padded: conflict-free both ways
    int d = t & 255, vg = t >> 8;

    // inproj
#pragma unroll
    for (int r = 0; r < 3; r++) {
        int v = vg + r * 4;
        unsigned p = g_v2gi[v];
        int pi = p / WW, pj = p - pi * WW;
        const float* xb = x + ((long)(b * CC) * HH + pi) * WW + pj;
        float acc = __ldg(&bin[d]);
        acc = fmaf(__ldg(xb + 0L*HH*WW), __ldg(&Win[0*DD + d]), acc);
        acc = fmaf(__ldg(xb + 1L*HH*WW), __ldg(&Win[1*DD + d]), acc);
        acc = fmaf(__ldg(xb + 2L*HH*WW), __ldg(&Win[2*DD + d]), acc);
        acc = fmaf(__ldg(xb + 3L*HH*WW), __ldg(&Win[3*DD + d]), acc);
        h[v * DD + d] = acc;
    }
    __syncthreads();

    int md = t >> 2, mc = t & 3;              // staging role: one float4 per thread per chunk

    for (int l = 0; l < 4; l++) {
        // aggregate (elementwise in d)
#pragma unroll
        for (int r = 0; r < 3; r++) {
            int v = vg + r * 4;
            float s = h[c_nbr[v][0]*DD + d] + h[c_nbr[v][1]*DD + d]
                    + h[c_nbr[v][2]*DD + d] + h[c_nbr[v][3]*DD + d]
                    + h[c_nbr[v][4]*DD + d];
            agg[v * DD + d] = s * 0.2f;
        }
        __syncthreads();

        const float4* a0 = reinterpret_cast<const float4*>(agg + (vg    ) * DD);
        const float4* a1 = reinterpret_cast<const float4*>(agg + (vg + 4) * DD);
        const float4* a2 = reinterpret_cast<const float4*>(agg + (vg + 8) * DD);
        float4 q0 = make_float4(0,0,0,0), q1 = q0, q2 = q0;

        for (int kc = 0; kc < 16; kc++) {
            // stage WT[l][md][kc*16 + mc*4 ..+4] -> tile4[mc][md]  (coalesced LDG.128)
            tile4[mc][md] = g_WT4[(l * DD + md) * (DD/4) + kc * 4 + mc];
            __syncthreads();
#pragma unroll
            for (int c = 0; c < 4; c++) {
                float4 w  = tile4[c][d];          // consecutive d -> conflict-free
                float4 f0 = a0[kc * 4 + c];       // warp-uniform broadcast
                float4 f1 = a1[kc * 4 + c];
                float4 f2 = a2[kc * 4 + c];
                q0.x = fmaf(f0.x, w.x, q0.x); q0.y = fmaf(f0.y, w.y, q0.y);
                q0.z = fmaf(f0.z, w.z, q0.z); q0.w = fmaf(f0.w, w.w, q0.w);
                q1.x = fmaf(f1.x, w.x, q1.x); q1.y = fmaf(f1.y, w.y, q1.y);
                q1.z = fmaf(f1.z, w.z, q1.z); q1.w = fmaf(f1.w, w.w, q1.w);
                q2.x = fmaf(f2.x, w.x, q2.x); q2.y = fmaf(f2.y, w.y, q2.y);
                q2.z = fmaf(f2.z, w.z, q2.z); q2.w = fmaf(f2.w, w.w, q2.w);
            }
            __syncthreads();
        }
        float bias = __ldg(&bl[l * DD + d]);
        float r0 = ((q0.x + q0.y) + (q0.z + q0.w)) + bias;
        float r1 = ((q1.x + q1.y) + (q1.z + q1.w)) + bias;
        float r2 = ((q2.x + q2.y) + (q2.z + q2.w)) + bias;
        h[(vg    ) * DD + d] += fmaxf(r0, 0.0f);   // exclusive (v,d) ownership
        h[(vg + 4) * DD + d] += fmaxf(r1, 0.0f);
        h[(vg + 8) * DD + d] += fmaxf(r2, 0.0f);
        __syncthreads();
    }

    // outproj: one warp per (v,c), 48 pairs over 32 warps
    int w = t >> 5, lane = t & 31;
    for (int pair = w; pair < NV * CC; pair += 32) {
        int v = pair >> 2, c = pair & 3;
        float s = 0.f;
#pragma unroll
        for (int k = lane; k < DD; k += 32)
            s = fmaf(h[v * DD + k], __ldg(&Wout[k * CC + c]), s);
#pragma unroll
        for (int off = 16; off > 0; off >>= 1)
            s += __shfl_down_sync(0xFFFFFFFFu, s, off);
        if (lane == 0) g_nodes[(b * NV + v) * CC + c] = s + __ldg(&bout[c]);
    }
}

// ---- K3: output scatter — one block serves all 4 c-planes of one batch ----
__global__ void __launch_bounds__(256) k_scatter(float* __restrict__ out) {
    int b = blockIdx.y;
    __shared__ float sval[NV][CC];
    if (threadIdx.x < NV * CC)
        sval[threadIdx.x >> 2][threadIdx.x & 3] = g_nodes[b * NV * CC + threadIdx.x];
    __syncthreads();
    float4* out4 = reinterpret_cast<float4*>(out);
    const uchar4* vmap4 = reinterpret_cast<const uchar4*>(g_vmap);
    int q0 = blockIdx.x * 512 + threadIdx.x;
#pragma unroll
    for (int r = 0; r < 2; r++) {
        int q = q0 + r * 256;
        if (q < NQ4) {
            uchar4 vm = vmap4[q];
#pragma unroll
            for (int c = 0; c < CC; c++) {
                float4 o;
                o.x = sval[vm.x][c]; o.y = sval[vm.y][c];
                o.z = sval[vm.z][c]; o.w = sval[vm.w][c];
                out4[(long)(b * CC + c) * NQ4 + q] = o;
            }
        }
    }
}

extern "C" void kernel_launch(void* const* d_in, const int* in_sizes, int n_in,
                              void* d_out, int out_size) {
    const float* x        = (const float*)d_in[0];
    const float* W_in     = (const float*)d_in[2];
    const float* b_in     = (const float*)d_in[3];
    const float* W_layers = (const float*)d_in[4];
    const float* b_layers = (const float*)d_in[5];
    const float* W_out    = (const float*)d_in[6];
    const float* b_out    = (const float*)d_in[7];
    float* out = (float*)d_out;

    k_prep<<<268, 256>>>(W_layers);
    k_vmap<<<dim3((WW + 255) / 256, HH), 256>>>();
    k_gnn<<<BB, 1024>>>(x, W_in, b_in, b_layers, W_out, b_out);
    k_scatter<<<dim3((NQ4 + 511) / 512, BB), 256>>>(out);
}

// round 11
// speedup vs baseline: 1.6526x; 1.0548x over previous
#include <cuda_runtime.h>
#include <stdint.h>

#define HH 721
#define WW 1440
#define NPTS (HH*WW)
#define NQ4  (NPTS/4)
#define BB 16
#define CC 4
#define DD 256
#define NV 12
#define GNN_BLOCKS 32
#define PI_D 3.141592653589793
#define TWOPI_D (2.0*PI_D)

static __device__ double        g_dla2d[NV][HH];
static __device__ double        g_dlo2d[NV][WW];
static __device__ float         g_dla2f[NV][HH];
static __device__ float         g_dlo2f[NV][WW];
static __device__ unsigned int  g_v2gi[NV];
static __device__ unsigned char g_vmap[NPTS];
static __device__ float         g_nodes[BB*NV*CC];
static __device__ float         g_hn[BB*NV*DD];     // cross-block h exchange
static __device__ unsigned int  g_bar;              // grid barrier counter (reset by k_prep)

__constant__ signed char c_vcode[NV][3] = {
    {-1,2,0},{1,2,0},{-1,-2,0},{1,-2,0},{0,-1,2},{0,1,2},
    {0,-1,-2},{0,1,-2},{2,0,-1},{2,0,1},{-2,0,-1},{-2,0,1}};
__constant__ int c_nbr[NV][5] = {
    {11,5,1,7,10},{0,5,7,9,8},{11,10,3,4,6},{9,4,2,6,8},
    {5,11,3,9,2},{0,11,1,9,4},{10,7,3,2,8},{0,1,10,6,8},
    {7,1,3,6,9},{1,5,3,4,8},{0,7,11,2,6},{0,5,10,2,4}};

// ---- K0: per-vertex f64 tables + separable argmin; also resets grid barrier ----
__global__ void __launch_bounds__(256) k_prep() {
    int v = blockIdx.x;
    int t = threadIdx.x;
    if (v == 0 && t == 0) g_bar = 0u;      // reset persistent barrier each launch

    __shared__ double svlat, svlon;
    __shared__ double rv[8];
    __shared__ int    ri[8];
    __shared__ int    sbest[2];

    if (t == 0) {
        float phi = (float)((1.0 + sqrt(5.0)) * 0.5);
        float c[3];
#pragma unroll
        for (int k = 0; k < 3; k++) {
            int cd = c_vcode[v][k];
            float m = (cd == 2 || cd == -2) ? phi : 1.0f;
            c[k] = (cd == 0) ? 0.0f : (cd < 0 ? -m : m);
        }
        float n2 = __fadd_rn(__fadd_rn(__fmul_rn(c[0],c[0]), __fmul_rn(c[1],c[1])),
                             __fmul_rn(c[2],c[2]));
        float nrm = __fsqrt_rn(n2);
        float x = __fdiv_rn(c[0],nrm), y = __fdiv_rn(c[1],nrm), z = __fdiv_rn(c[2],nrm);
        float s = __fsqrt_rn(__fsub_rn(1.0f, __fmul_rn(z,z)));
        svlat = (double)__fmul_rn(2.0f, atan2f(z, __fadd_rn(1.0f, s)));   // XLA asin
        svlon = (double)atan2f(y, x);
    }
    __syncthreads();
    double vlat = svlat, vlon = svlon;

    double bla = 1.0e300, blo = 1.0e300; int bia = 0, bio = 0;
    double dla_s = __ddiv_rn(PI_D, 720.0);
    double dlo_s = __ddiv_rn(TWOPI_D, 1439.0);
    for (int li = t; li < HH; li += 256) {
        double lat = __dadd_rn(-(PI_D*0.5), __dmul_rn((double)li, dla_s));
        if (li == 360) lat = 1.0e-12;            // symmetry row pinned positive (validated)
        double dla = __dsub_rn(lat, vlat);
        double q = __dmul_rn(dla, dla);
        g_dla2d[v][li] = q;
        g_dla2f[v][li] = (float)q;
        if (q < bla) { bla = q; bia = li; }
    }
    for (int lj = t; lj < WW; lj += 256) {
        double lon = __dadd_rn(-PI_D, __dmul_rn((double)lj, dlo_s));
        double raw = __dadd_rn(__dsub_rn(lon, vlon), PI_D);
        double r = raw;
        if (raw >= TWOPI_D)   r = __dsub_rn(raw, TWOPI_D);
        else if (raw < 0.0)   r = __dadd_rn(raw, TWOPI_D);
        double dlo = __dsub_rn(r, PI_D);
        double q = __dmul_rn(dlo, dlo);
        g_dlo2d[v][lj] = q;
        g_dlo2f[v][lj] = (float)q;
        if (q < blo) { blo = q; bio = lj; }
    }
#pragma unroll
    for (int pass = 0; pass < 2; pass++) {
        double bv = pass ? blo : bla;
        int    bi = pass ? bio : bia;
#pragma unroll
        for (int off = 16; off > 0; off >>= 1) {
            double ov = __shfl_down_sync(0xFFFFFFFFu, bv, off);
            int    oi = __shfl_down_sync(0xFFFFFFFFu, bi, off);
            if (ov < bv || (ov == bv && oi < bi)) { bv = ov; bi = oi; }
        }
        if ((t & 31) == 0) { rv[t >> 5] = bv; ri[t >> 5] = bi; }
        __syncthreads();
        if (t < 8) {
            bv = rv[t]; bi = ri[t];
#pragma unroll
            for (int off = 4; off > 0; off >>= 1) {
                double ov = __shfl_down_sync(0xFFu, bv, off);
                int    oi = __shfl_down_sync(0xFFu, bi, off);
                if (ov < bv || (ov == bv && oi < bi)) { bv = ov; bi = oi; }
            }
            if (t == 0) sbest[pass] = bi;
        }
        __syncthreads();
    }
    if (t == 0) g_v2gi[v] = (unsigned)(sbest[0] * WW + sbest[1]);
}

// ---- K1: per-pixel nearest vertex; f32 fast path + exact f64 fallback (unchanged) ----
__global__ void __launch_bounds__(256) k_vmap() {
    __shared__ float sa[NV];
    __shared__ float sb[NV][256];
    int t = threadIdx.x;
    int li = blockIdx.y;
    int lj0 = blockIdx.x * 256;
    if (t < NV) sa[t] = g_dla2f[t][li];
#pragma unroll
    for (int v = 0; v < NV; v++) {
        int lj = lj0 + t;
        sb[v][t] = (lj < WW) ? g_dlo2f[v][lj] : 1.0e30f;
    }
    __syncthreads();

    int lj = lj0 + t;
    if (lj >= WW) return;
    float b1 = 1.0e30f, b2 = 1.0e30f; int bv = 0;
#pragma unroll
    for (int v = 0; v < NV; v++) {
        float s = sa[v] + sb[v][t];
        if (s < b1) { b2 = b1; b1 = s; bv = v; }
        else if (s < b2) { b2 = s; }
    }
    if (b2 - b1 < 1.0e-4f) {   // ambiguous in f32 -> exact f64 reference compare
        double best = 1.0e300; bv = 0;
#pragma unroll
        for (int v = 0; v < NV; v++) {
            double s = __dadd_rn(g_dla2d[v][li], g_dlo2d[v][lj]);
            if (s < best) { best = s; bv = v; }
        }
    }
    int p = li * WW + lj;
    int j = p / HH;             // g2v = reshape(lon,lat).T scramble
    int i = p - j * HH;
    g_vmap[i * WW + j] = (unsigned char)bv;
}

// ---- grid barrier across GNN_BLOCKS co-resident blocks ----
__device__ __forceinline__ void gbar(unsigned target) {
    __syncthreads();
    if (threadIdx.x == 0) {
        __threadfence();
        atomicAdd(&g_bar, 1u);
        while (atomicAdd(&g_bar, 0u) < target) { }
        __threadfence();
    }
    __syncthreads();
}

// ---- K2: persistent fused GNN. 32 blocks (16 b x 2 d-halves) x 256 threads. ----
// Matmul: lanes = consecutive d -> W[k][d] loads perfectly coalesced (original layout,
// no transpose); agg[k] warp-uniform smem broadcasts; 6 v-accumulators per thread.
__global__ void __launch_bounds__(256) k_gnn(const float* __restrict__ x,
                                             const float* __restrict__ Win,
                                             const float* __restrict__ bin,
                                             const float* __restrict__ Wlayers,
                                             const float* __restrict__ bl,
                                             const float* __restrict__ Wout,
                                             const float* __restrict__ bout) {
    int blk = blockIdx.x;
    int b = blk >> 1, half = blk & 1;
    int t = threadIdx.x;
    __shared__ __align__(16) float h_s[NV * DD];
    __shared__ __align__(16) float agg_s[NV * DD];

    // inproj: both halves compute the FULL h0 (cheap, avoids an exchange)
#pragma unroll
    for (int v = 0; v < NV; v++) {
        unsigned p = g_v2gi[v];
        int pi = p / WW, pj = p - pi * WW;
        const float* xb = x + ((long)(b * CC) * HH + pi) * WW + pj;
        float acc = __ldg(&bin[t]);
        acc = fmaf(__ldg(xb + 0L*HH*WW), __ldg(&Win[0*DD + t]), acc);
        acc = fmaf(__ldg(xb + 1L*HH*WW), __ldg(&Win[1*DD + t]), acc);
        acc = fmaf(__ldg(xb + 2L*HH*WW), __ldg(&Win[2*DD + t]), acc);
        acc = fmaf(__ldg(xb + 3L*HH*WW), __ldg(&Win[3*DD + t]), acc);
        h_s[v * DD + t] = acc;
    }
    __syncthreads();

    int d  = half * 128 + (t & 127);   // this block's d-half; lanes consecutive -> coalesced W
    int vb = (t >> 7) * 6;             // 6 vertices per thread
    const float4* a4 = reinterpret_cast<const float4*>(agg_s);

    for (int l = 0; l < 4; l++) {
        // aggregate (full, elementwise in d)
#pragma unroll
        for (int v = 0; v < NV; v++) {
            float s = h_s[c_nbr[v][0]*DD + t] + h_s[c_nbr[v][1]*DD + t]
                    + h_s[c_nbr[v][2]*DD + t] + h_s[c_nbr[v][3]*DD + t]
                    + h_s[c_nbr[v][4]*DD + t];
            agg_s[v * DD + t] = s * 0.2f;
        }
        __syncthreads();

        const float* Wl = Wlayers + l * DD * DD;
        float acc[6] = {0.f, 0.f, 0.f, 0.f, 0.f, 0.f};
#pragma unroll 4
        for (int kq = 0; kq < DD/4; kq++) {
            float w0 = __ldg(Wl + (kq*4 + 0) * DD + d);
            float w1 = __ldg(Wl + (kq*4 + 1) * DD + d);
            float w2 = __ldg(Wl + (kq*4 + 2) * DD + d);
            float w3 = __ldg(Wl + (kq*4 + 3) * DD + d);
#pragma unroll
            for (int r = 0; r < 6; r++) {
                float4 a = a4[(vb + r) * (DD/4) + kq];   // warp-uniform broadcast
                acc[r] = fmaf(a.x, w0, fmaf(a.y, w1, fmaf(a.z, w2, fmaf(a.w, w3, acc[r]))));
            }
        }
        float bias = __ldg(&bl[l * DD + d]);
#pragma unroll
        for (int r = 0; r < 6; r++) {
            int v = vb + r;
            g_hn[(b * NV + v) * DD + d] = h_s[v * DD + d] + fmaxf(acc[r] + bias, 0.0f);
        }

        gbar((unsigned)(GNN_BLOCKS * (l + 1)));

        // reload full h for next stage
        float4* h4 = reinterpret_cast<float4*>(h_s);
        const float4* gh4 = reinterpret_cast<const float4*>(g_hn + b * NV * DD);
#pragma unroll
        for (int idx = t; idx < NV * DD / 4; idx += 256) h4[idx] = gh4[idx];
        __syncthreads();
    }

    // outproj: 48 (v,c) pairs split between the two halves; one warp per 3 pairs
    int w = t >> 5, lane = t & 31;
#pragma unroll
    for (int r = 0; r < 3; r++) {
        int pair = half * 24 + w * 3 + r;
        int v = pair >> 2, c = pair & 3;
        float s = 0.f;
#pragma unroll
        for (int k = lane; k < DD; k += 32)
            s = fmaf(h_s[v * DD + k], __ldg(&Wout[k * CC + c]), s);
#pragma unroll
        for (int off = 16; off > 0; off >>= 1)
            s += __shfl_down_sync(0xFFFFFFFFu, s, off);
        if (lane == 0) g_nodes[(b * NV + v) * CC + c] = s + __ldg(&bout[c]);
    }
}

// ---- K3: output scatter — streaming stores, one block serves all 4 c-planes ----
__global__ void __launch_bounds__(256) k_scatter(float* __restrict__ out) {
    int b = blockIdx.y;
    __shared__ float sval[NV][CC];
    if (threadIdx.x < NV * CC)
        sval[threadIdx.x >> 2][threadIdx.x & 3] = g_nodes[b * NV * CC + threadIdx.x];
    __syncthreads();
    float4* out4 = reinterpret_cast<float4*>(out);
    const uchar4* vmap4 = reinterpret_cast<const uchar4*>(g_vmap);
    int q0 = blockIdx.x * 512 + threadIdx.x;
#pragma unroll
    for (int r = 0; r < 2; r++) {
        int q = q0 + r * 256;
        if (q < NQ4) {
            uchar4 vm = vmap4[q];
#pragma unroll
            for (int c = 0; c < CC; c++) {
                float4 o;
                o.x = sval[vm.x][c]; o.y = sval[vm.y][c];
                o.z = sval[vm.z][c]; o.w = sval[vm.w][c];
                __stcs(&out4[(long)(b * CC + c) * NQ4 + q], o);
            }
        }
    }
}

extern "C" void kernel_launch(void* const* d_in, const int* in_sizes, int n_in,
                              void* d_out, int out_size) {
    const float* x        = (const float*)d_in[0];
    const float* W_in     = (const float*)d_in[2];
    const float* b_in     = (const float*)d_in[3];
    const float* W_layers = (const float*)d_in[4];
    const float* b_layers = (const float*)d_in[5];
    const float* W_out    = (const float*)d_in[6];
    const float* b_out    = (const float*)d_in[7];
    float* out = (float*)d_out;

    k_prep<<<NV, 256>>>();
    k_vmap<<<dim3((WW + 255) / 256, HH), 256>>>();
    k_gnn<<<GNN_BLOCKS, 256>>>(x, W_in, b_in, W_layers, b_layers, W_out, b_out);
    k_scatter<<<dim3((NQ4 + 511) / 512, BB), 256>>>(out);
}